// round 3
// baseline (speedup 1.0000x reference)
#include <cuda_runtime.h>

// out = ReLU(LayerNorm(emb[:, :, :256] @ W_enc + b_enc) * gamma + beta)
// The reference's kNN/gather path is a provable no-op (pooled == embeddings).
//
// Shapes: M = B*S = 16384 rows, K = 256, N = 512, all fp32.
// One fused kernel: GEMM (f32x2 packed FMA) + warp-level LayerNorm + ReLU.

#define BM      32
#define BK      16
#define KDIM    256
#define NDIM    512
#define DROW    512      // embeddings row stride (we use first 256)
#define THREADS 256
#define LN_EPS  1e-5f

typedef unsigned long long u64;

__device__ __forceinline__ u64 pack2(float lo, float hi) {
    u64 r; asm("mov.b64 %0,{%1,%2};" : "=l"(r) : "f"(lo), "f"(hi)); return r;
}
__device__ __forceinline__ void unpack2(u64 v, float& lo, float& hi) {
    asm("mov.b64 {%0,%1},%2;" : "=f"(lo), "=f"(hi) : "l"(v));
}
__device__ __forceinline__ u64 fma2(u64 a, u64 b, u64 c) {
    u64 r; asm("fma.rn.f32x2 %0,%1,%2,%3;" : "=l"(r) : "l"(a), "l"(b), "l"(c)); return r;
}

__global__ __launch_bounds__(THREADS, 2)
void fused_gemm_ln_relu(const float* __restrict__ emb,
                        const float* __restrict__ W,      // [256, 512]
                        const float* __restrict__ bias,   // [512]
                        const float* __restrict__ gamma,  // [512]
                        const float* __restrict__ beta,   // [512]
                        float* __restrict__ out) {
    __shared__ float ash[BM][BK + 4];   // padded: row stride 20 floats = 80B (16B aligned)
    __shared__ float wsh[BK][NDIM];

    const int tid  = threadIdx.x;
    const int warp = tid >> 5;          // 8 warps; warp owns rows 4w..4w+3
    const int lane = tid & 31;          // lane owns cols 4*lane + 128*j, j=0..3
    const int m0   = blockIdx.x * BM;

    // acc[r][c]: row r (0..3), c = j*2 + pair -> cols 4*lane + 128*j + 2*pair + {0,1}
    u64 acc[4][8];
    #pragma unroll
    for (int r = 0; r < 4; r++)
        #pragma unroll
        for (int c = 0; c < 8; c++) acc[r][c] = 0ull;

    for (int kc = 0; kc < KDIM; kc += BK) {
        // --- A tile: BM x BK = 512 floats; threads 0..127 each do one float4 ---
        if (tid < (BM * BK / 4)) {
            const int row = tid / (BK / 4);
            const int q   = tid % (BK / 4);
            const float4 v = *(const float4*)&emb[(size_t)(m0 + row) * DROW + kc + q * 4];
            *(float4*)&ash[row][q * 4] = v;
        }
        // --- W tile: BK x 512 = 8192 floats = 2048 float4; 8 per thread, coalesced ---
        #pragma unroll
        for (int i = 0; i < 8; i++) {
            const int idx = tid + i * THREADS;   // float4 index
            const int row = idx >> 7;            // /128
            const int c4  = idx & 127;
            *(float4*)&wsh[row][c4 * 4] =
                *(const float4*)&W[(size_t)(kc + row) * NDIM + c4 * 4];
        }
        __syncthreads();

        #pragma unroll
        for (int kk = 0; kk < BK; kk++) {
            u64 a2[4];
            #pragma unroll
            for (int r = 0; r < 4; r++) {
                const float av = ash[warp * 4 + r][kk];   // warp-broadcast LDS
                a2[r] = pack2(av, av);
            }
            u64 w2[8];
            #pragma unroll
            for (int j = 0; j < 4; j++) {
                // LDS.128, lane-contiguous 16B -> conflict-free
                const ulonglong2 wv = *(const ulonglong2*)&wsh[kk][lane * 4 + 128 * j];
                w2[j * 2]     = wv.x;
                w2[j * 2 + 1] = wv.y;
            }
            #pragma unroll
            for (int r = 0; r < 4; r++)
                #pragma unroll
                for (int c = 0; c < 8; c++)
                    acc[r][c] = fma2(a2[r], w2[c], acc[r][c]);
        }
        __syncthreads();
    }

    // --- Epilogue: bias, LayerNorm (warp owns full rows), affine, ReLU ---
    float bz[16], gm[16], bt[16];
    #pragma unroll
    for (int j = 0; j < 4; j++) {
        const int col = lane * 4 + 128 * j;
        *(float4*)&bz[j * 4] = *(const float4*)&bias[col];
        *(float4*)&gm[j * 4] = *(const float4*)&gamma[col];
        *(float4*)&bt[j * 4] = *(const float4*)&beta[col];
    }

    #pragma unroll
    for (int r = 0; r < 4; r++) {
        float h[16];
        #pragma unroll
        for (int c = 0; c < 8; c++) {
            float lo, hi;
            unpack2(acc[r][c], lo, hi);
            const int j = c >> 1, pair = c & 1;
            h[j * 4 + pair * 2 + 0] = lo;
            h[j * 4 + pair * 2 + 1] = hi;
        }
        float s = 0.f, sq = 0.f;
        #pragma unroll
        for (int i = 0; i < 16; i++) {
            h[i] += bz[i];
            s  += h[i];
            sq += h[i] * h[i];
        }
        // warp reduction over the 32 lanes (full row of 512)
        #pragma unroll
        for (int o = 16; o > 0; o >>= 1) {
            s  += __shfl_xor_sync(0xFFFFFFFFu, s,  o);
            sq += __shfl_xor_sync(0xFFFFFFFFu, sq, o);
        }
        const float mu   = s * (1.0f / NDIM);
        const float var  = sq * (1.0f / NDIM) - mu * mu;
        const float rstd = rsqrtf(var + LN_EPS);

        float y[16];
        #pragma unroll
        for (int i = 0; i < 16; i++) {
            float v = (h[i] - mu) * rstd * gm[i] + bt[i];
            y[i] = fmaxf(v, 0.0f);
        }
        const size_t orow = (size_t)(m0 + warp * 4 + r) * NDIM;
        #pragma unroll
        for (int j = 0; j < 4; j++) {
            *(float4*)&out[orow + lane * 4 + 128 * j] = *(float4*)&y[j * 4];
        }
    }
}

extern "C" void kernel_launch(void* const* d_in, const int* in_sizes, int n_in,
                              void* d_out, int out_size) {
    // metadata order: embeddings, W_proj, b_proj, W_enc, b_enc, ln_gamma, ln_beta
    const float* emb   = (const float*)d_in[0];
    const float* W_enc = (const float*)d_in[3];
    const float* b_enc = (const float*)d_in[4];
    const float* gamma = (const float*)d_in[5];
    const float* beta  = (const float*)d_in[6];
    float* out = (float*)d_out;

    const int M = in_sizes[0] / DROW;       // B*S = 16384
    const int grid = M / BM;                // 512 blocks
    fused_gemm_ln_relu<<<grid, THREADS>>>(emb, W_enc, b_enc, gamma, beta, out);
}

// round 4
// speedup vs baseline: 1.1027x; 1.1027x over previous
#include <cuda_runtime.h>
#include <cstdint>

// out = ReLU(LayerNorm(emb[:, :, :256] @ W_enc + b_enc) * gamma + beta)
// (reference kNN/gather path is a provable no-op: pooled == embeddings)
//
// M = 16384, K = 256, N = 512, fp32.
// Fused GEMM (packed f32x2 FMA) + warp-row LayerNorm + ReLU.
// R3: vectorized A broadcast (LDS.128) + cp.async double-buffered tiles.

#define BM      32
#define BK      16
#define KDIM    256
#define NDIM    512
#define DROW    512
#define THREADS 256
#define NT      (KDIM / BK)     // 16 k-tiles
#define LN_EPS  1e-5f

// dynamic smem layout (floats):
//   wsh: [2][BK][NDIM]  = 16384 floats
//   ash: [2][BM][20]    =  1280 floats  (row stride 20 floats = 80B, 16B-aligned)
#define WSH_FLOATS (2 * BK * NDIM)
#define ASH_STRIDE 20
#define SMEM_FLOATS (WSH_FLOATS + 2 * BM * ASH_STRIDE)
#define SMEM_BYTES  (SMEM_FLOATS * 4)

typedef unsigned long long u64;

__device__ __forceinline__ u64 pack2(float lo, float hi) {
    u64 r; asm("mov.b64 %0,{%1,%2};" : "=l"(r) : "f"(lo), "f"(hi)); return r;
}
__device__ __forceinline__ void unpack2(u64 v, float& lo, float& hi) {
    asm("mov.b64 {%0,%1},%2;" : "=f"(lo), "=f"(hi) : "l"(v));
}
__device__ __forceinline__ u64 fma2(u64 a, u64 b, u64 c) {
    u64 r; asm("fma.rn.f32x2 %0,%1,%2,%3;" : "=l"(r) : "l"(a), "l"(b), "l"(c)); return r;
}
__device__ __forceinline__ uint32_t smem_u32(const void* p) {
    uint32_t a;
    asm("{ .reg .u64 t; cvta.to.shared.u64 t, %1; cvt.u32.u64 %0, t; }" : "=r"(a) : "l"(p));
    return a;
}
__device__ __forceinline__ void cp16(uint32_t dst, const void* src) {
    asm volatile("cp.async.cg.shared.global [%0], [%1], 16;" :: "r"(dst), "l"(src));
}
__device__ __forceinline__ void cp_commit() { asm volatile("cp.async.commit_group;"); }
template <int N>
__device__ __forceinline__ void cp_wait() { asm volatile("cp.async.wait_group %0;" :: "n"(N)); }

__global__ __launch_bounds__(THREADS, 2)
void fused_gemm_ln_relu(const float* __restrict__ emb,
                        const float* __restrict__ W,      // [256, 512]
                        const float* __restrict__ bias,
                        const float* __restrict__ gamma,
                        const float* __restrict__ beta,
                        float* __restrict__ out) {
    extern __shared__ float smem[];
    float* wsh = smem;                       // [2][BK][NDIM]
    float* ash = smem + WSH_FLOATS;          // [2][BM][ASH_STRIDE]

    const int tid  = threadIdx.x;
    const int warp = tid >> 5;               // 8 warps; warp owns rows 4w..4w+3
    const int lane = tid & 31;               // lane owns cols 4*lane + 128*j
    const int m0   = blockIdx.x * BM;

    // precompute this thread's cp.async destinations / source offsets
    // W tile: 2048 float4 per tile, 8 per thread
    // A tile:  128 float4 per tile, threads 0..127 one each
    const int a_row = tid >> 2;              // for tid < 128
    const int a_q   = tid & 3;

    u64 acc[4][8];
    #pragma unroll
    for (int r = 0; r < 4; r++)
        #pragma unroll
        for (int c = 0; c < 8; c++) acc[r][c] = 0ull;

    // ---- prefetch helper (tile t into buffer t&1) ----
    auto prefetch = [&](int t) {
        const int kc  = t * BK;
        const int buf = t & 1;
        float* wdst = wsh + buf * (BK * NDIM);
        #pragma unroll
        for (int i = 0; i < 8; i++) {
            const int idx = tid + i * THREADS;   // float4 index in tile
            const int row = idx >> 7;            // /128
            const int c4  = idx & 127;
            cp16(smem_u32(&wdst[row * NDIM + c4 * 4]),
                 &W[(size_t)(kc + row) * NDIM + c4 * 4]);
        }
        if (tid < (BM * BK / 4)) {
            float* adst = ash + buf * (BM * ASH_STRIDE);
            cp16(smem_u32(&adst[a_row * ASH_STRIDE + a_q * 4]),
                 &emb[(size_t)(m0 + a_row) * DROW + kc + a_q * 4]);
        }
    };

    prefetch(0);
    cp_commit();

    for (int t = 0; t < NT; t++) {
        if (t + 1 < NT) { prefetch(t + 1); cp_commit(); cp_wait<1>(); }
        else            { cp_wait<0>(); }
        __syncthreads();

        const int buf = t & 1;
        const float* wb = wsh + buf * (BK * NDIM);
        const float* ab = ash + buf * (BM * ASH_STRIDE);

        #pragma unroll
        for (int kk4 = 0; kk4 < BK / 4; kk4++) {
            // one LDS.128 per row loads 4 k-values (warp-uniform broadcast)
            float a4[4][4];
            #pragma unroll
            for (int r = 0; r < 4; r++)
                *(float4*)a4[r] =
                    *(const float4*)&ab[(warp * 4 + r) * ASH_STRIDE + kk4 * 4];

            #pragma unroll
            for (int u = 0; u < 4; u++) {
                const int kk = kk4 * 4 + u;
                u64 w2[8];
                #pragma unroll
                for (int j = 0; j < 4; j++) {
                    const ulonglong2 wv =
                        *(const ulonglong2*)&wb[kk * NDIM + lane * 4 + 128 * j];
                    w2[j * 2]     = wv.x;
                    w2[j * 2 + 1] = wv.y;
                }
                u64 a2[4];
                #pragma unroll
                for (int r = 0; r < 4; r++) a2[r] = pack2(a4[r][u], a4[r][u]);
                #pragma unroll
                for (int r = 0; r < 4; r++)
                    #pragma unroll
                    for (int c = 0; c < 8; c++)
                        acc[r][c] = fma2(a2[r], w2[c], acc[r][c]);
            }
        }
        __syncthreads();
    }

    // --- Epilogue: bias, warp-row LayerNorm, affine, ReLU ---
    float bz[16], gm[16], bt[16];
    #pragma unroll
    for (int j = 0; j < 4; j++) {
        const int col = lane * 4 + 128 * j;
        *(float4*)&bz[j * 4] = *(const float4*)&bias[col];
        *(float4*)&gm[j * 4] = *(const float4*)&gamma[col];
        *(float4*)&bt[j * 4] = *(const float4*)&beta[col];
    }

    #pragma unroll
    for (int r = 0; r < 4; r++) {
        float h[16];
        #pragma unroll
        for (int c = 0; c < 8; c++) {
            float lo, hi;
            unpack2(acc[r][c], lo, hi);
            const int j = c >> 1, pair = c & 1;
            h[j * 4 + pair * 2 + 0] = lo;
            h[j * 4 + pair * 2 + 1] = hi;
        }
        float s = 0.f, sq = 0.f;
        #pragma unroll
        for (int i = 0; i < 16; i++) {
            h[i] += bz[i];
            s  += h[i];
            sq += h[i] * h[i];
        }
        #pragma unroll
        for (int o = 16; o > 0; o >>= 1) {
            s  += __shfl_xor_sync(0xFFFFFFFFu, s,  o);
            sq += __shfl_xor_sync(0xFFFFFFFFu, sq, o);
        }
        const float mu   = s * (1.0f / NDIM);
        const float var  = sq * (1.0f / NDIM) - mu * mu;
        const float rstd = rsqrtf(var + LN_EPS);

        float y[16];
        #pragma unroll
        for (int i = 0; i < 16; i++) {
            float v = (h[i] - mu) * rstd * gm[i] + bt[i];
            y[i] = fmaxf(v, 0.0f);
        }
        const size_t orow = (size_t)(m0 + warp * 4 + r) * NDIM;
        #pragma unroll
        for (int j = 0; j < 4; j++)
            *(float4*)&out[orow + lane * 4 + 128 * j] = *(float4*)&y[j * 4];
    }
}

extern "C" void kernel_launch(void* const* d_in, const int* in_sizes, int n_in,
                              void* d_out, int out_size) {
    const float* emb   = (const float*)d_in[0];
    const float* W_enc = (const float*)d_in[3];
    const float* b_enc = (const float*)d_in[4];
    const float* gamma = (const float*)d_in[5];
    const float* beta  = (const float*)d_in[6];
    float* out = (float*)d_out;

    cudaFuncSetAttribute(fused_gemm_ln_relu,
                         cudaFuncAttributeMaxDynamicSharedMemorySize, SMEM_BYTES);

    const int M = in_sizes[0] / DROW;       // 16384
    const int grid = M / BM;                // 512
    fused_gemm_ln_relu<<<grid, THREADS, SMEM_BYTES>>>(emb, W_enc, b_enc, gamma, beta, out);
}

// round 6
// speedup vs baseline: 1.9017x; 1.7247x over previous
#include <cuda_runtime.h>
#include <cuda_bf16.h>
#include <cstdint>

// out = ReLU(LayerNorm(emb[:, :, :256] @ W_enc + b_enc) * gamma + beta)
// (reference kNN/gather path is a provable no-op: pooled == embeddings)
//
// R5: mma.sync bf16x3 (hi*hi + hi*lo + lo*hi) — portable HMMA path, since this
// harness targets plain sm_103 (no tcgen05 'a' features available).
//
// M=16384, K=256, N=512. CTA: 64 rows x N=512. 512 thr / 16 warps, warp 32x64.

#define KDIM    256
#define NDIM    512
#define DROW    512
#define BM      64
#define THREADS 512
#define NSTAGE  16          // K / 16
#define LN_EPS  1e-5f

typedef uint32_t u32;
typedef unsigned long long u64;

// prepped W: [n][k] bf16, hi and lo parts (256 KB each, L2-resident)
__device__ __nv_bfloat16 g_Whi[NDIM * KDIM];
__device__ __nv_bfloat16 g_Wlo[NDIM * KDIM];

// ---- smem layout (bytes) ----
// A_hi [64][256] bf16 swizzled : 0     .. 32767
// A_lo                         : 32768 .. 65535
// B ring: 4 stages x 32KB      : 65536 .. 196607   (stage: 512 n x 64B)
// epilogue reuses [0..133119] as h[64][520] f32
#define SM_ALO  32768
#define SM_B    65536
#define SMEM_TOTAL (65536 + 4 * 32768)
#define HSTRIDE 520

__device__ __forceinline__ u32 smem_u32(const void* p) {
    u32 a;
    asm("{ .reg .u64 t; cvta.to.shared.u64 t, %1; cvt.u32.u64 %0, t; }" : "=r"(a) : "l"(p));
    return a;
}
__device__ __forceinline__ void cp16(u32 dst, const void* src) {
    asm volatile("cp.async.cg.shared.global [%0], [%1], 16;" :: "r"(dst), "l"(src));
}
__device__ __forceinline__ void cp_commit() { asm volatile("cp.async.commit_group;"); }
template <int N>
__device__ __forceinline__ void cp_wait() { asm volatile("cp.async.wait_group %0;" :: "n"(N)); }

__device__ __forceinline__ void ldsm4(u32* r, u32 addr) {
    asm volatile("ldmatrix.sync.aligned.m8n8.x4.shared.b16 {%0,%1,%2,%3}, [%4];"
                 : "=r"(r[0]), "=r"(r[1]), "=r"(r[2]), "=r"(r[3]) : "r"(addr));
}
__device__ __forceinline__ void mma16816(float* d, const u32* a, const u32* b) {
    asm volatile(
        "mma.sync.aligned.m16n8k16.row.col.f32.bf16.bf16.f32 "
        "{%0,%1,%2,%3}, {%4,%5,%6,%7}, {%8,%9}, {%0,%1,%2,%3};"
        : "+f"(d[0]), "+f"(d[1]), "+f"(d[2]), "+f"(d[3])
        : "r"(a[0]), "r"(a[1]), "r"(a[2]), "r"(a[3]), "r"(b[0]), "r"(b[1]));
}

// ---------------- prep: W [k][n] f32 -> Whi/Wlo [n][k] bf16 ----------------
__global__ void prep_w(const float* __restrict__ W) {
    const int idx = blockIdx.x * blockDim.x + threadIdx.x;   // 0..32767
    const int n  = idx & 511;
    const int k4 = idx >> 9;                                  // 0..63
    unsigned short h[4], l[4];
    #pragma unroll
    for (int e = 0; e < 4; e++) {
        const float w = W[(size_t)(k4 * 4 + e) * NDIM + n];   // coalesced over n
        const __nv_bfloat16 hi = __float2bfloat16(w);
        const __nv_bfloat16 lo = __float2bfloat16(w - __bfloat162float(hi));
        h[e] = __bfloat16_as_ushort(hi);
        l[e] = __bfloat16_as_ushort(lo);
    }
    uint2 hp = make_uint2((u32)h[0] | ((u32)h[1] << 16), (u32)h[2] | ((u32)h[3] << 16));
    uint2 lp = make_uint2((u32)l[0] | ((u32)l[1] << 16), (u32)l[2] | ((u32)l[3] << 16));
    *(uint2*)&g_Whi[(size_t)n * KDIM + k4 * 4] = hp;
    *(uint2*)&g_Wlo[(size_t)n * KDIM + k4 * 4] = lp;
}

// ---------------- main fused GEMM + LN + ReLU ----------------
__global__ __launch_bounds__(THREADS, 1)
void gemm_ln_mma(const float* __restrict__ emb,
                 const float* __restrict__ bias,
                 const float* __restrict__ gamma,
                 const float* __restrict__ beta,
                 float* __restrict__ out) {
    extern __shared__ char smem[];
    const u32 sb   = smem_u32(smem);
    const int tid  = threadIdx.x;
    const int lane = tid & 31;
    const int w    = tid >> 5;       // 16 warps
    const int wr   = w >> 3;         // 0..1 : row block of 32
    const int wc   = w & 7;          // 0..7 : col block of 64
    const int m0   = blockIdx.x * BM;

    // ---- B stage loader: 2048 x 16B chunks, 4 per thread ----
    auto cpB = [&](int s) {
        const u32 bbase = sb + SM_B + (s & 3) * 32768;
        #pragma unroll
        for (int j = 0; j < 4; j++) {
            const int i  = tid + THREADS * j;
            const int n  = i >> 2;
            const int cb = i & 3;
            const char* src = (const char*)(cb < 2 ? g_Whi : g_Wlo)
                            + (size_t)n * 512 + s * 32 + (cb & 1) * 16;
            cp16(bbase + n * 64 + (((u32)cb ^ ((n >> 1) & 3)) << 4), src);
        }
    };

    cpB(0); cp_commit();
    cpB(1); cp_commit();
    cpB(2); cp_commit();

    // ---- A: load 64x256 f32, split to bf16 hi/lo into swizzled smem ----
    // chunk c = k/8 (16B, 8 bf16); phys chunk = c ^ (row & 7)
    #pragma unroll
    for (int i = 0; i < 8; i++) {
        const int f   = tid + THREADS * i;    // float4 index, 4096 total
        const int row = f >> 6;
        const int q   = f & 63;               // float4 within row (k = 4q)
        const float4 v = *(const float4*)&emb[(size_t)(m0 + row) * DROW + q * 4];
        unsigned short h[4], l[4];
        const float vv[4] = {v.x, v.y, v.z, v.w};
        #pragma unroll
        for (int e = 0; e < 4; e++) {
            const __nv_bfloat16 hi = __float2bfloat16(vv[e]);
            const __nv_bfloat16 lo = __float2bfloat16(vv[e] - __bfloat162float(hi));
            h[e] = __bfloat16_as_ushort(hi);
            l[e] = __bfloat16_as_ushort(lo);
        }
        const u32 addr = sb + row * 512 + ((((u32)(q >> 1)) ^ (row & 7)) << 4) + (q & 1) * 8;
        asm volatile("st.shared.v2.b32 [%0], {%1, %2};" :: "r"(addr),
                     "r"((u32)h[0] | ((u32)h[1] << 16)), "r"((u32)h[2] | ((u32)h[3] << 16)));
        asm volatile("st.shared.v2.b32 [%0], {%1, %2};" :: "r"(addr + SM_ALO),
                     "r"((u32)l[0] | ((u32)l[1] << 16)), "r"((u32)l[2] | ((u32)l[3] << 16)));
    }

    // ---- per-lane ldmatrix geometry ----
    // A: row = wr*32 + mt*16 + ((lane>>3)&1)*8 + (lane&7); khalf = lane>>4
    const int a_row0  = wr * 32 + ((lane >> 3) & 1) * 8 + (lane & 7);
    const int a_swz   = a_row0 & 7;
    const int a_khalf = lane >> 4;
    // B: n = wc*64 + p*16 + ((lane>>4)&1)*8 + (lane&7); cb = (lane>>3)&1
    u32 offB[4];
    #pragma unroll
    for (int p = 0; p < 4; p++) {
        const int n  = wc * 64 + p * 16 + ((lane >> 4) & 1) * 8 + (lane & 7);
        const int cb = (lane >> 3) & 1;
        offB[p] = n * 64 + (((u32)cb ^ ((n >> 1) & 3)) << 4);
    }

    float d[2][8][4];
    #pragma unroll
    for (int mt = 0; mt < 2; mt++)
        #pragma unroll
        for (int j = 0; j < 8; j++)
            #pragma unroll
            for (int e = 0; e < 4; e++) d[mt][j][e] = 0.0f;

    // ---- mainloop over 16 k-stages ----
    #pragma unroll 1
    for (int s = 0; s < NSTAGE; s++) {
        if (s <= 13)      cp_wait<2>();
        else if (s == 14) cp_wait<1>();
        else              cp_wait<0>();
        __syncthreads();                       // B[s] visible; prev-iter reads done
        if (s + 3 < NSTAGE) { cpB(s + 3); cp_commit(); }   // writes buf read 2 iters ago

        u32 ah[2][4], al[2][4];
        #pragma unroll
        for (int mt = 0; mt < 2; mt++) {
            const int row = a_row0 + mt * 16;
            const u32 ad = sb + row * 512 + ((((u32)(2 * s + a_khalf)) ^ a_swz) << 4);
            ldsm4(ah[mt], ad);
            ldsm4(al[mt], ad + SM_ALO);
        }
        const u32 bbase = sb + SM_B + (s & 3) * 32768;
        #pragma unroll
        for (int p = 0; p < 4; p++) {
            u32 bh[4], bl[4];
            ldsm4(bh, bbase + offB[p]);
            ldsm4(bl, (bbase + offB[p]) ^ 32);   // lo chunks = hi chunks ^ 32B
            #pragma unroll
            for (int mt = 0; mt < 2; mt++)
                #pragma unroll
                for (int e = 0; e < 2; e++) {
                    float* dd = d[mt][p * 2 + e];
                    mma16816(dd, ah[mt], &bh[2 * e]);   // hi*hi
                    mma16816(dd, ah[mt], &bl[2 * e]);   // hi*lo
                    mma16816(dd, al[mt], &bh[2 * e]);   // lo*hi
                }
        }
    }

    // ---- epilogue: acc -> smem h[64][520], then warp-row LN + ReLU ----
    __syncthreads();
    float* hb = (float*)smem;
    #pragma unroll
    for (int mt = 0; mt < 2; mt++)
        #pragma unroll
        for (int j = 0; j < 8; j++) {
            const int row = wr * 32 + mt * 16 + (lane >> 2);
            const int col = wc * 64 + j * 8 + (lane & 3) * 2;
            *(float2*)&hb[row * HSTRIDE + col]       = make_float2(d[mt][j][0], d[mt][j][1]);
            *(float2*)&hb[(row + 8) * HSTRIDE + col] = make_float2(d[mt][j][2], d[mt][j][3]);
        }
    __syncthreads();

    float bz[16], gm[16], bt[16];
    #pragma unroll
    for (int j = 0; j < 4; j++) {
        const int col = lane * 4 + 128 * j;
        *(float4*)&bz[j * 4] = *(const float4*)&bias[col];
        *(float4*)&gm[j * 4] = *(const float4*)&gamma[col];
        *(float4*)&bt[j * 4] = *(const float4*)&beta[col];
    }

    #pragma unroll
    for (int r = 0; r < 4; r++) {
        const int row = w * 4 + r;            // 16 warps x 4 rows = 64
        float h[16];
        float s = 0.f, sq = 0.f;
        #pragma unroll
        for (int j = 0; j < 4; j++) {
            float4 v = *(const float4*)&hb[row * HSTRIDE + lane * 4 + 128 * j];
            h[j * 4 + 0] = v.x + bz[j * 4 + 0];
            h[j * 4 + 1] = v.y + bz[j * 4 + 1];
            h[j * 4 + 2] = v.z + bz[j * 4 + 2];
            h[j * 4 + 3] = v.w + bz[j * 4 + 3];
        }
        #pragma unroll
        for (int i = 0; i < 16; i++) { s += h[i]; sq += h[i] * h[i]; }
        #pragma unroll
        for (int o = 16; o > 0; o >>= 1) {
            s  += __shfl_xor_sync(0xFFFFFFFFu, s,  o);
            sq += __shfl_xor_sync(0xFFFFFFFFu, sq, o);
        }
        const float mu   = s * (1.0f / NDIM);
        const float var  = sq * (1.0f / NDIM) - mu * mu;
        const float rstd = rsqrtf(var + LN_EPS);
        float y[16];
        #pragma unroll
        for (int i = 0; i < 16; i++)
            y[i] = fmaxf((h[i] - mu) * rstd * gm[i] + bt[i], 0.0f);
        const size_t orow = (size_t)(m0 + row) * NDIM;
        #pragma unroll
        for (int j = 0; j < 4; j++)
            *(float4*)&out[orow + lane * 4 + 128 * j] = *(float4*)&y[j * 4];
    }
}

extern "C" void kernel_launch(void* const* d_in, const int* in_sizes, int n_in,
                              void* d_out, int out_size) {
    const float* emb   = (const float*)d_in[0];
    const float* W_enc = (const float*)d_in[3];
    const float* b_enc = (const float*)d_in[4];
    const float* gamma = (const float*)d_in[5];
    const float* beta  = (const float*)d_in[6];
    float* out = (float*)d_out;

    cudaFuncSetAttribute(gemm_ln_mma,
                         cudaFuncAttributeMaxDynamicSharedMemorySize, SMEM_TOTAL);

    prep_w<<<128, 256>>>(W_enc);

    const int M = in_sizes[0] / DROW;       // 16384
    gemm_ln_mma<<<M / BM, THREADS, SMEM_TOTAL>>>(emb, b_enc, gamma, beta, out);
}